// round 1
// baseline (speedup 1.0000x reference)
#include <cuda_runtime.h>

#define B_DIM   256
#define OUT_DIM 256
#define IN_DIM  256
#define G_DIM   8

// Scratch (no allocation allowed): xn/k table transposed [i][b], and A/B tables.
__device__ float2 g_xnk[IN_DIM * B_DIM];                  // .x = tanh(x)*log2e, .y = bitcast(k*4)
__device__ float  g_ABt[OUT_DIM * IN_DIM * 20];           // [o][i][ A0..A8 | B0..B8 | s | base*ln2 ]

// ---------------------------------------------------------------------------
// Kernel 1: xn = tanh(x), segment index k = #(grid points <= xn)
// ---------------------------------------------------------------------------
__global__ void k_prep_x(const float* __restrict__ x, const float* __restrict__ grid)
{
    int idx = blockIdx.x * blockDim.x + threadIdx.x;      // idx = i*B + b (write-coalesced)
    if (idx >= IN_DIM * B_DIM) return;
    int i = idx >> 8;
    int b = idx & 255;
    float xn = tanhf(x[b * IN_DIM + i]);
    float g0 = grid[0];
    float g7 = grid[G_DIM - 1];
    float inv_h = (float)(G_DIM - 1) / (g7 - g0);
    int k = 1 + (int)floorf((xn - g0) * inv_h);           // count of grid pts <= xn
    k = max(0, min(8, k));
    float2 v;
    v.x = xn * 1.44269504088896340736f;                   // pre-scale by log2(e)
    v.y = __int_as_float(k * 4);                          // byte offset into A row
    g_xnk[idx] = v;
}

// ---------------------------------------------------------------------------
// Kernel 2: per (o,i): A_k = sum_{g<k} w_g e^{s*grid_g}, B_k = sum_{g>=k} w_g e^{-s*grid_g}
// ---------------------------------------------------------------------------
__global__ void k_prep_tab(const float* __restrict__ w,
                           const float* __restrict__ scaler,
                           const float* __restrict__ base,
                           const float* __restrict__ grid)
{
    int idx = blockIdx.x * blockDim.x + threadIdx.x;      // idx = o*IN + i
    if (idx >= OUT_DIM * IN_DIM) return;
    float s = scaler[idx];
    float p[G_DIM], q[G_DIM];
#pragma unroll
    for (int g = 0; g < G_DIM; g++) {
        float gv = grid[g];
        float wv = w[idx * G_DIM + g];
        p[g] = wv * __expf(s * gv);
        q[g] = wv * __expf(-s * gv);
    }
    float* dst = &g_ABt[idx * 20];
    float a = 0.f;
#pragma unroll
    for (int k = 0; k < 9; k++) {                         // prefix sums: A_k
        dst[k] = a;
        if (k < 8) a += p[k];
    }
    float bs = 0.f;
    dst[9 + 8] = 0.f;
#pragma unroll
    for (int k = 7; k >= 0; k--) {                        // suffix sums: B_k
        bs += q[k];
        dst[9 + k] = bs;
    }
    dst[18] = s;
    dst[19] = base[idx] * 0.69314718055994530942f;        // ln2 (undo the log2e in xn')
}

// ---------------------------------------------------------------------------
// Kernel 3: main contraction. Thread = one (b,o); loop i; 1-reg accumulator.
//   contribution(b,o,i) = A_k * 2^{-s*xn'} + B_k * 2^{s*xn'} + base' * xn'
// ---------------------------------------------------------------------------
#define BT 32
#define OT 8
#define IC 32

__global__ __launch_bounds__(256)
void k_main(float* __restrict__ out)
{
    __shared__ float2 sh_xnk[IC][BT];
    __shared__ float  sh_ab[IC * OT * 20];

    int tid     = threadIdx.x;
    int o_local = tid & (OT - 1);
    int b_local = tid >> 3;
    int o0 = blockIdx.x * OT;
    int b0 = blockIdx.y * BT;

    const float* abrow = &sh_ab[o_local * 20];
    float acc = 0.f;

    for (int i0 = 0; i0 < IN_DIM; i0 += IC) {
        // --- stage xn/k for this (i-chunk, b-tile) ---
#pragma unroll
        for (int e = tid; e < IC * BT; e += 256) {
            int ii = e >> 5;
            int bb = e & 31;
            sh_xnk[ii][bb] = g_xnk[(i0 + ii) * B_DIM + b0 + bb];
        }
        // --- stage A/B/s/base rows for this (i-chunk, o-tile) ---
#pragma unroll
        for (int e = tid; e < IC * OT * 20; e += 256) {
            int ii  = e / 160;
            int rem = e - ii * 160;
            int oo  = rem / 20;
            int kk  = rem - oo * 20;
            sh_ab[e] = g_ABt[((o0 + oo) * IN_DIM + (i0 + ii)) * 20 + kk];
        }
        __syncthreads();

#pragma unroll
        for (int ii = 0; ii < IC; ii++) {
            float2 xk = sh_xnk[ii][b_local];
            int koff = __float_as_int(xk.y);
            const char* rp = (const char*)(abrow + ii * OT * 20);
            float A  = *(const float*)(rp + koff);            // A_k
            float Bv = *(const float*)(rp + 36 + koff);       // B_k (9 floats later)
            float2 sb = *(const float2*)(rp + 72);            // {s, base*ln2}
            float t = sb.x * xk.x;                            // s * xn * log2e
            float u, r;
            asm("ex2.approx.f32 %0, %1;" : "=f"(u) : "f"(t)); // e^{ s*xn}
            asm("rcp.approx.f32 %0, %1;" : "=f"(r) : "f"(u)); // e^{-s*xn}
            acc = fmaf(A,  r,    acc);
            acc = fmaf(Bv, u,    acc);
            acc = fmaf(sb.y, xk.x, acc);                      // base * xn
        }
        __syncthreads();
    }

    out[(b0 + b_local) * OUT_DIM + (o0 + o_local)] = acc;
}

// ---------------------------------------------------------------------------
extern "C" void kernel_launch(void* const* d_in, const int* in_sizes, int n_in,
                              void* d_out, int out_size)
{
    const float* x      = (const float*)d_in[0];
    const float* w      = (const float*)d_in[1];
    const float* scaler = (const float*)d_in[2];
    const float* base   = (const float*)d_in[3];
    const float* grid   = (const float*)d_in[4];
    float* out = (float*)d_out;

    k_prep_x  <<<(IN_DIM * B_DIM + 255) / 256, 256>>>(x, grid);
    k_prep_tab<<<(OUT_DIM * IN_DIM + 255) / 256, 256>>>(w, scaler, base, grid);

    dim3 g(OUT_DIM / OT, B_DIM / BT);   // 32 x 8 = 256 CTAs
    k_main<<<g, 256>>>(out);
}

// round 4
// speedup vs baseline: 1.5129x; 1.5129x over previous
#include <cuda_runtime.h>

#define B_DIM   256
#define OUT_DIM 256
#define IN_DIM  256
#define G_DIM   8
#define LOG2E   1.44269504088896340736f
#define LN2     0.69314718055994530942f

// Scratch (no allocation allowed).
// g_xnk: transposed [i][b]; .x = tanh(x)*log2e, .y = bitcast(k*8) (byte offset into AB pairs)
__device__ float2 g_xnk[IN_DIM * B_DIM];
// g_AB: SoA [20][OUT*IN]; component c: c=2k -> A_k, c=2k+1 -> B_k (k=0..8), c=18 -> s, c=19 -> base*ln2
__device__ float  g_AB[20 * OUT_DIM * IN_DIM];

// ---------------------------------------------------------------------------
// Kernel 1: xn = tanh(x), segment index k; coalesced read, tile-transposed write
// ---------------------------------------------------------------------------
__global__ __launch_bounds__(256)
void k_prep_x(const float* __restrict__ x, const float* __restrict__ grid)
{
    __shared__ float2 tile[32][33];
    int tx = threadIdx.x & 31;
    int ty = threadIdx.x >> 5;          // 0..7
    int b0 = blockIdx.x * 32;
    int i0 = blockIdx.y * 32;

    float g0 = __ldg(&grid[0]);
    float g7 = __ldg(&grid[G_DIM - 1]);
    float inv_h = (float)(G_DIM - 1) / (g7 - g0);

#pragma unroll
    for (int r = 0; r < 32; r += 8) {
        int b = b0 + ty + r;
        int i = i0 + tx;
        float xn = tanhf(x[b * IN_DIM + i]);            // coalesced
        int k = 1 + (int)floorf((xn - g0) * inv_h);     // #(grid pts <= xn)
        k = max(0, min(8, k));
        tile[ty + r][tx] = make_float2(xn * LOG2E, __int_as_float(k * 8));
    }
    __syncthreads();
#pragma unroll
    for (int r = 0; r < 32; r += 8) {
        int i = i0 + ty + r;
        int b = b0 + tx;
        g_xnk[i * B_DIM + b] = tile[tx][ty + r];        // coalesced
    }
}

// ---------------------------------------------------------------------------
// Kernel 2: per (o,i): A_k = sum_{g<k} w_g e^{s*g_g}, B_k = sum_{g>=k} w_g e^{-s*g_g}
// SoA output, fully coalesced stores.
// ---------------------------------------------------------------------------
__global__ __launch_bounds__(256)
void k_prep_tab(const float* __restrict__ w,
                const float* __restrict__ scaler,
                const float* __restrict__ base,
                const float* __restrict__ grid)
{
    int idx = blockIdx.x * blockDim.x + threadIdx.x;    // idx = o*IN + i
    if (idx >= OUT_DIM * IN_DIM) return;
    float s = scaler[idx];

    float4 w0 = *(const float4*)(w + idx * G_DIM);
    float4 w1 = *(const float4*)(w + idx * G_DIM + 4);
    float wv[G_DIM] = {w0.x, w0.y, w0.z, w0.w, w1.x, w1.y, w1.z, w1.w};

    float p[G_DIM], q[G_DIM];
#pragma unroll
    for (int g = 0; g < G_DIM; g++) {
        float gv = __ldg(&grid[g]);
        p[g] = wv[g] * __expf(s * gv);
        q[g] = wv[g] * __expf(-s * gv);
    }
    // prefix A_k, suffix B_k
    float A[9], Bv[9];
    A[0] = 0.f;
#pragma unroll
    for (int k = 0; k < 8; k++) A[k + 1] = A[k] + p[k];
    Bv[8] = 0.f;
#pragma unroll
    for (int k = 7; k >= 0; k--) Bv[k] = Bv[k + 1] + q[k];

    const int N = OUT_DIM * IN_DIM;
#pragma unroll
    for (int k = 0; k < 9; k++) {
        g_AB[(2 * k    ) * N + idx] = A[k];
        g_AB[(2 * k + 1) * N + idx] = Bv[k];
    }
    g_AB[18 * N + idx] = s;
    g_AB[19 * N + idx] = base[idx] * LN2;
}

// ---------------------------------------------------------------------------
// Kernel 3: main contraction. Thread = one (b,o); loop i; 1-reg accumulator.
//   contribution(b,o,i) = A_k * 2^{-t} + B_k * 2^{t} + base' * xn',  t = s*xn'
// ---------------------------------------------------------------------------
#define BT 32
#define OT 8
#define IC 32
#define ABROW 20           // floats per (ii,o) cell
#define IISTR 162          // padded floats per ii slice (8*20 + 2); 162 mod 32 = 2

__global__ __launch_bounds__(256, 2)
void k_main(float* __restrict__ out)
{
    __shared__ float2 sh_xnk[IC][BT];
    __shared__ float  sh_ab[IC * IISTR];

    int tid     = threadIdx.x;
    int o_local = tid & (OT - 1);
    int b_local = tid >> 3;
    int o0 = blockIdx.x * OT;
    int b0 = blockIdx.y * BT;

    const char* rp0 = (const char*)(sh_ab + o_local * ABROW);
    float acc = 0.f;
    const int N = OUT_DIM * IN_DIM;

    for (int i0 = 0; i0 < IN_DIM; i0 += IC) {
        // stage xnk: [ii][bb], coalesced global (b contiguous), conflict-free store
#pragma unroll
        for (int j = 0; j < (IC * BT) / 256; j++) {
            int e  = tid + j * 256;
            int ii = e >> 5;
            int bb = e & 31;
            sh_xnk[ii][bb] = g_xnk[(i0 + ii) * B_DIM + b0 + bb];
        }
        // stage AB table: 20 comps x 8 o x 32 ii; coalesced global reads (ii contiguous)
#pragma unroll
        for (int j = 0; j < (20 * OT * IC) / 256; j++) {
            int e  = tid + j * 256;
            int ii = e & 31;
            int oo = (e >> 5) & 7;
            int c  = e >> 8;
            sh_ab[ii * IISTR + oo * ABROW + c] =
                g_AB[c * N + (o0 + oo) * IN_DIM + i0 + ii];
        }
        __syncthreads();

#pragma unroll
        for (int ii = 0; ii < IC; ii++) {
            float2 xk = sh_xnk[ii][b_local];
            int koff = __float_as_int(xk.y);                       // k*8 bytes
            const char* rp = rp0 + ii * (IISTR * 4);
            float2 ab = *(const float2*)(rp + koff);               // {A_k, B_k}
            float2 sb = *(const float2*)(rp + 18 * 4);             // {s, base*ln2}
            float t = sb.x * xk.x;
            float u, r;
            asm("ex2.approx.f32 %0, %1;" : "=f"(u) : "f"(t));      // e^{ s*xn}
            asm("rcp.approx.f32 %0, %1;" : "=f"(r) : "f"(u));      // e^{-s*xn}
            acc = fmaf(ab.x, r, acc);
            acc = fmaf(ab.y, u, acc);
            acc = fmaf(sb.y, xk.x, acc);
        }
        __syncthreads();
    }

    out[(b0 + b_local) * OUT_DIM + (o0 + o_local)] = acc;
}

// ---------------------------------------------------------------------------
extern "C" void kernel_launch(void* const* d_in, const int* in_sizes, int n_in,
                              void* d_out, int out_size)
{
    const float* x      = (const float*)d_in[0];
    const float* w      = (const float*)d_in[1];
    const float* scaler = (const float*)d_in[2];
    const float* base   = (const float*)d_in[3];
    const float* grid   = (const float*)d_in[4];
    float* out = (float*)d_out;

    dim3 gpx(B_DIM / 32, IN_DIM / 32);
    k_prep_x  <<<gpx, 256>>>(x, grid);
    k_prep_tab<<<(OUT_DIM * IN_DIM + 255) / 256, 256>>>(w, scaler, base, grid);

    dim3 g(OUT_DIM / OT, B_DIM / BT);   // 32 x 8 = 256 CTAs
    k_main<<<g, 256>>>(out);
}

// round 5
// speedup vs baseline: 1.7986x; 1.1889x over previous
#include <cuda_runtime.h>

#define B_DIM   256
#define OUT_DIM 256
#define IN_DIM  256
#define G_DIM   8
#define LOG2E   1.44269504088896340736f
#define LN2     0.69314718055994530942f

#define BT 32            // b-tile per CTA
#define OT 8             // o-tile per CTA
#define IC 32            // i-chunk
#define ABROW 20         // floats per (ii,oo) cell: A0,B0,...,A8,B8,s,base*ln2
#define IISTR 162        // padded floats per ii slice (8*20 + 2); 162 mod 32 = 2

__device__ __forceinline__ float rcp_f(float a) {
    float r; asm("rcp.approx.f32 %0, %1;" : "=f"(r) : "f"(a)); return r;
}
__device__ __forceinline__ float ex2_f(float a) {
    float r; asm("ex2.approx.f32 %0, %1;" : "=f"(r) : "f"(a)); return r;
}
// tanh(x) = 1 - 2/(e^{2x}+1); saturates correctly at +/-inf, abs err ~1e-7
__device__ __forceinline__ float tanh_fast(float x) {
    float e = __expf(2.0f * x);
    return 1.0f - __fdividef(2.0f, e + 1.0f);
}

__global__ __launch_bounds__(256, 2)
void k_fused(const float* __restrict__ x,
             const float* __restrict__ w,
             const float* __restrict__ scaler,
             const float* __restrict__ base,
             const float* __restrict__ grid,
             float* __restrict__ out)
{
    __shared__ float2 sh_xnk[IC][BT + 1];    // [ii][bb], pad -> stride 33 float2
    __shared__ float  sh_ab[IC * IISTR];

    const int tid = threadIdx.x;
    const int o0  = blockIdx.x * OT;
    const int b0  = blockIdx.y * BT;

    // consumer roles
    const int o_local = tid & (OT - 1);
    const int b_local = tid >> 3;            // 0..31
    // prep roles
    const int xb  = tid >> 3;                // 0..31  : b row for x load
    const int xi4 = (tid & 7) * 4;           // 0,4..28: i quad for x load
    const int iiA = tid & 31;                // AB row: i within chunk
    const int ooA = tid >> 5;                // AB row: o within tile

    const float g0    = __ldg(grid);
    const float g7    = __ldg(grid + (G_DIM - 1));
    const float step  = (g7 - g0) * (1.0f / (float)(G_DIM - 1));
    const float inv_h = (float)(G_DIM - 1) / (g7 - g0);

    // ---- prefetch chunk 0 into registers ----
    float4 xq  = *(const float4*)(x + (b0 + xb) * IN_DIM + xi4);
    int    row = (o0 + ooA) * IN_DIM + iiA;
    float4 w0r = *(const float4*)(w + row * G_DIM);
    float4 w1r = *(const float4*)(w + row * G_DIM + 4);
    float  sr  = scaler[row];
    float  br  = base[row];

    float acc = 0.0f;

#pragma unroll 1
    for (int c = 0; c < IN_DIM / IC; c++) {
        const int i0 = c * IC;

        // ---- write xnk for this chunk (from regs) ----
        float xv[4] = {xq.x, xq.y, xq.z, xq.w};
#pragma unroll
        for (int v = 0; v < 4; v++) {
            float xn = tanh_fast(xv[v]);
            int k = 1 + __float2int_rd((xn - g0) * inv_h);   // #(grid pts <= xn)
            k = max(0, min(8, k));
            sh_xnk[xi4 + v][xb] = make_float2(xn * LOG2E, __int_as_float(k * 8));
        }

        // ---- compute A/B prefix tables for this chunk (from regs) ----
        {
            float wv[G_DIM] = {w0r.x, w0r.y, w0r.z, w0r.w, w1r.x, w1r.y, w1r.z, w1r.w};
            float Ep = __expf(sr * step);        // e^{ s*step}
            float ep = __expf(sr * g0);          // e^{ s*g0}
            float Eq = rcp_f(Ep);                // e^{-s*step}
            float eq = rcp_f(ep);                // e^{-s*g0}
            float p[G_DIM], q[G_DIM];
#pragma unroll
            for (int g = 0; g < G_DIM; g++) {
                p[g] = wv[g] * ep;  ep *= Ep;    // w_g * e^{ s*grid_g}
                q[g] = wv[g] * eq;  eq *= Eq;    // w_g * e^{-s*grid_g}
            }
            float A[9], Bv[9];
            A[0] = 0.f;
#pragma unroll
            for (int k = 0; k < 8; k++) A[k + 1] = A[k] + p[k];
            Bv[8] = 0.f;
#pragma unroll
            for (int k = 7; k >= 0; k--) Bv[k] = Bv[k + 1] + q[k];

            float2* cell = (float2*)(sh_ab + iiA * IISTR + ooA * ABROW);
#pragma unroll
            for (int k = 0; k < 9; k++) cell[k] = make_float2(A[k], Bv[k]);
            cell[9] = make_float2(sr, br * LN2);
        }

        // ---- prefetch next chunk (overlaps the consume phase) ----
        if (c + 1 < IN_DIM / IC) {
            xq  = *(const float4*)(x + (b0 + xb) * IN_DIM + i0 + IC + xi4);
            row = (o0 + ooA) * IN_DIM + i0 + IC + iiA;
            w0r = *(const float4*)(w + row * G_DIM);
            w1r = *(const float4*)(w + row * G_DIM + 4);
            sr  = scaler[row];
            br  = base[row];
        }
        __syncthreads();

        // ---- consume: contribution = A_k*2^{-t} + B_k*2^{t} + base'*xn',  t = s*xn' ----
        const char* rp0 = (const char*)(sh_ab + o_local * ABROW);
#pragma unroll
        for (int ii = 0; ii < IC; ii++) {
            float2 xk = sh_xnk[ii][b_local];
            const char* rp = rp0 + ii * (IISTR * 4);
            float2 ab = *(const float2*)(rp + __float_as_int(xk.y));  // {A_k, B_k}
            float2 sb = *(const float2*)(rp + 18 * 4);                // {s, base*ln2}
            float t = sb.x * xk.x;
            float u = ex2_f(t);          // e^{ s*xn}
            float r = rcp_f(u);          // e^{-s*xn}
            acc = fmaf(ab.x, r, acc);
            acc = fmaf(ab.y, u, acc);
            acc = fmaf(sb.y, xk.x, acc);
        }
        __syncthreads();
    }

    out[(b0 + b_local) * OUT_DIM + (o0 + o_local)] = acc;
}

// ---------------------------------------------------------------------------
extern "C" void kernel_launch(void* const* d_in, const int* in_sizes, int n_in,
                              void* d_out, int out_size)
{
    const float* x      = (const float*)d_in[0];
    const float* w      = (const float*)d_in[1];
    const float* scaler = (const float*)d_in[2];
    const float* base   = (const float*)d_in[3];
    const float* grid   = (const float*)d_in[4];
    float* out = (float*)d_out;

    dim3 g(OUT_DIM / OT, B_DIM / BT);   // 32 x 8 = 256 CTAs
    k_fused<<<g, 256>>>(x, w, scaler, base, grid, out);
}